// round 1
// baseline (speedup 1.0000x reference)
#include <cuda_runtime.h>

#define BB 16384
#define CC 4
#define HH 8
#define TT 120
#define ALPHA 0.2f
#define THRESH 0.5f

// One thread per (b, c). State [H]=8 floats in registers. 120 sequential steps.
// Noise [T,B,C,H]: each thread reads its 8 contiguous floats per step via 2x float4,
// software-prefetched one step ahead. Class competition resolved via quad shuffles.
__global__ __launch_bounds__(256) void accum_rnn_kernel(
    const float* __restrict__ logits,       // [B,C]
    const float* __restrict__ input_scale,  // [1]
    const float* __restrict__ noise_std,    // [1]
    const float* __restrict__ ipw,          // [H,1]
    const float* __restrict__ ipb,          // [H]
    const float* __restrict__ W,            // [H,H] (k,h)
    const float* __restrict__ cw,           // [H,1]
    const float* __restrict__ evw,          // [1,H]
    const float* __restrict__ evb,          // [1]
    const float* __restrict__ cbias,        // [C,H]
    const float* __restrict__ cmat,         // [C,C]
    const float* __restrict__ noise,        // [T,B,C,H]
    float* __restrict__ out)                // [B,C]
{
    const int g = blockIdx.x * blockDim.x + threadIdx.x;   // g = b*C + c
    const int c = g & 3;

    const float scale = input_scale[0];
    const float nstd  = noise_std[0];
    const float eb    = evb[0];

    // Loop-invariant weights into registers (uniform across warp -> L1 broadcast).
    float w[HH][HH];
#pragma unroll
    for (int k = 0; k < HH; k++)
#pragma unroll
        for (int h = 0; h < HH; h++)
            w[k][h] = W[k * HH + h];

    float ew[HH], cwv[HH], inp[HH];
    float r = logits[g] * scale;
    r = r > 0.0f ? r : 0.0f;
#pragma unroll
    for (int h = 0; h < HH; h++) {
        ew[h]  = evw[h];
        cwv[h] = cw[h];
        inp[h] = r * ipw[h] + ipb[h] + cbias[c * HH + h];
    }
    // competition column c: cmat[c'][c]
    float cm0 = cmat[0 * CC + c];
    float cm1 = cmat[1 * CC + c];
    float cm2 = cmat[2 * CC + c];
    float cm3 = cmat[3 * CC + c];

    float s[HH];
#pragma unroll
    for (int h = 0; h < HH; h++) s[h] = 0.0f;

    float ev = eb;          // evidence of incoming state (state0 = 0)
    int cross = TT;         // first crossing step index; TT == never

    // Noise pointer: element offset g*8, per-step stride B*C*H floats.
    const float4* np = reinterpret_cast<const float4*>(noise) + (size_t)g * 2;
    const long STRIDE4 = (long)BB * CC * HH / 4;
    float4 n0 = np[0];
    float4 n1 = np[1];

    for (int t = 0; t < TT; t++) {
        // Current step's noise, then prefetch next step.
        float nz0 = n0.x, nz1 = n0.y, nz2 = n0.z, nz3 = n0.w;
        float nz4 = n1.x, nz5 = n1.y, nz6 = n1.z, nz7 = n1.w;
        if (t + 1 < TT) {
            np += STRIDE4;
            n0 = np[0];
            n1 = np[1];
        }

        // Gather the 4 class evidences within this lane quad.
        float e0 = __shfl_sync(0xffffffffu, ev, 0, 4);
        float e1 = __shfl_sync(0xffffffffu, ev, 1, 4);
        float e2 = __shfl_sync(0xffffffffu, ev, 2, 4);
        float e3 = __shfl_sync(0xffffffffu, ev, 3, 4);
        float comp = e0 * cm0 + e1 * cm1 + e2 * cm2 + e3 * cm3;

        float nz[HH] = {nz0, nz1, nz2, nz3, nz4, nz5, nz6, nz7};

        float ns[HH];
#pragma unroll
        for (int k = 0; k < HH; k++) {
            float a = inp[k] + comp * cwv[k] + nz[k] * nstd;
#pragma unroll
            for (int h = 0; h < HH; h++)
                a += s[h] * w[k][h];
            float cd = tanhf(a);
            ns[k] = s[k] + ALPHA * (cd - s[k]);
        }

        float nev = eb;
#pragma unroll
        for (int k = 0; k < HH; k++) {
            s[k] = ns[k];
            nev += s[k] * ew[k];
        }

        if (cross == TT && nev > THRESH) cross = t;
        ev = nev;
    }

    float td = (cross < TT) ? (float)(cross + 1) * 10.0f : (float)TT * 10.0f;
    out[g] = td * 0.001f;
}

extern "C" void kernel_launch(void* const* d_in, const int* in_sizes, int n_in,
                              void* d_out, int out_size) {
    const float* logits = (const float*)d_in[0];
    const float* iscale = (const float*)d_in[1];
    const float* nstd   = (const float*)d_in[2];
    const float* ipw    = (const float*)d_in[3];
    const float* ipb    = (const float*)d_in[4];
    const float* W      = (const float*)d_in[5];
    const float* cw     = (const float*)d_in[6];
    const float* evw    = (const float*)d_in[7];
    const float* evb    = (const float*)d_in[8];
    const float* cbias  = (const float*)d_in[9];
    const float* cmat   = (const float*)d_in[10];
    const float* noise  = (const float*)d_in[11];
    float* out = (float*)d_out;

    const int total = BB * CC;                 // 65536 threads
    const int threads = 256;
    const int blocks = total / threads;        // 256
    accum_rnn_kernel<<<blocks, threads>>>(
        logits, iscale, nstd, ipw, ipb, W, cw, evw, evb, cbias, cmat, noise, out);
}

// round 4
// speedup vs baseline: 1.5577x; 1.5577x over previous
#include <cuda_runtime.h>

#define BB 16384
#define CC 4
#define HH 8
#define TT 120
#define ALPHA 0.2f
#define THRESH 0.5f

// tanh(x) = 1 - 2/(e^{2x}+1). __expf -> FMUL+MUFU.EX2, __fdividef -> MUFU.RCP+FMUL.
// ~6 instructions, |err| ~ 1e-6: far below what could flip a threshold crossing
// at the 1e-3 rel-err gate. Saturates correctly for |x| large (e->inf => 1, e->0 => -1).
__device__ __forceinline__ float fast_tanh(float x) {
    float e = __expf(2.0f * x);
    return 1.0f - __fdividef(2.0f, e + 1.0f);
}

// One thread per (b, c). State [H]=8 floats in registers. 120 sequential steps.
// Noise [T,B,C,H]: each thread reads its 8 contiguous floats per step via 2x float4,
// software-prefetched one step ahead. Class competition resolved via quad shuffles.
// launch_bounds(128,4): cap regs at 128 so 4 CTAs (16 warps) co-reside per SM ->
// single wave over the grid instead of ~1.7 waves at 8 warps/SM.
__global__ __launch_bounds__(128, 4) void accum_rnn_kernel(
    const float* __restrict__ logits,       // [B,C]
    const float* __restrict__ input_scale,  // [1]
    const float* __restrict__ noise_std,    // [1]
    const float* __restrict__ ipw,          // [H,1]
    const float* __restrict__ ipb,          // [H]
    const float* __restrict__ W,            // [H,H] (k,h)
    const float* __restrict__ cw,           // [H,1]
    const float* __restrict__ evw,          // [1,H]
    const float* __restrict__ evb,          // [1]
    const float* __restrict__ cbias,        // [C,H]
    const float* __restrict__ cmat,         // [C,C]
    const float* __restrict__ noise,        // [T,B,C,H]
    float* __restrict__ out)                // [B,C]
{
    const int g = blockIdx.x * blockDim.x + threadIdx.x;   // g = b*C + c
    const int c = g & 3;

    const float scale = input_scale[0];
    const float nstd  = noise_std[0];
    const float eb    = evb[0];

    // Loop-invariant weights into registers (uniform across warp -> L1 broadcast).
    float w[HH][HH];
#pragma unroll
    for (int k = 0; k < HH; k++)
#pragma unroll
        for (int h = 0; h < HH; h++)
            w[k][h] = W[k * HH + h];

    float ew[HH], cwv[HH], inp[HH];
    float r = logits[g] * scale;
    r = r > 0.0f ? r : 0.0f;
#pragma unroll
    for (int h = 0; h < HH; h++) {
        ew[h]  = evw[h];
        cwv[h] = cw[h];
        inp[h] = r * ipw[h] + ipb[h] + cbias[c * HH + h];
    }
    // competition column c: cmat[c'][c]
    float cm0 = cmat[0 * CC + c];
    float cm1 = cmat[1 * CC + c];
    float cm2 = cmat[2 * CC + c];
    float cm3 = cmat[3 * CC + c];

    float s[HH];
#pragma unroll
    for (int h = 0; h < HH; h++) s[h] = 0.0f;

    float ev = eb;          // evidence of incoming state (state0 = 0)
    int cross = TT;         // first crossing step index; TT == never

    // Noise pointer: element offset g*8, per-step stride B*C*H floats.
    const float4* np = reinterpret_cast<const float4*>(noise) + (size_t)g * 2;
    const long STRIDE4 = (long)BB * CC * HH / 4;
    float4 n0 = np[0];
    float4 n1 = np[1];

    for (int t = 0; t < TT; t++) {
        // Current step's noise, then prefetch next step.
        float nz[HH] = {n0.x, n0.y, n0.z, n0.w, n1.x, n1.y, n1.z, n1.w};
        if (t + 1 < TT) {
            np += STRIDE4;
            n0 = np[0];
            n1 = np[1];
        }

        // Gather the 4 class evidences within this lane quad.
        float e0 = __shfl_sync(0xffffffffu, ev, 0, 4);
        float e1 = __shfl_sync(0xffffffffu, ev, 1, 4);
        float e2 = __shfl_sync(0xffffffffu, ev, 2, 4);
        float e3 = __shfl_sync(0xffffffffu, ev, 3, 4);
        float comp = e0 * cm0 + e1 * cm1 + e2 * cm2 + e3 * cm3;

        float ns[HH];
#pragma unroll
        for (int k = 0; k < HH; k++) {
            float a = inp[k] + comp * cwv[k] + nz[k] * nstd;
#pragma unroll
            for (int h = 0; h < HH; h++)
                a += s[h] * w[k][h];
            float cd = fast_tanh(a);
            ns[k] = s[k] + ALPHA * (cd - s[k]);
        }

        float nev = eb;
#pragma unroll
        for (int k = 0; k < HH; k++) {
            s[k] = ns[k];
            nev += s[k] * ew[k];
        }

        if (cross == TT && nev > THRESH) cross = t;
        ev = nev;
    }

    float td = (cross < TT) ? (float)(cross + 1) * 10.0f : (float)TT * 10.0f;
    out[g] = td * 0.001f;
}

extern "C" void kernel_launch(void* const* d_in, const int* in_sizes, int n_in,
                              void* d_out, int out_size) {
    const float* logits = (const float*)d_in[0];
    const float* iscale = (const float*)d_in[1];
    const float* nstd   = (const float*)d_in[2];
    const float* ipw    = (const float*)d_in[3];
    const float* ipb    = (const float*)d_in[4];
    const float* W      = (const float*)d_in[5];
    const float* cw     = (const float*)d_in[6];
    const float* evw    = (const float*)d_in[7];
    const float* evb    = (const float*)d_in[8];
    const float* cbias  = (const float*)d_in[9];
    const float* cmat   = (const float*)d_in[10];
    const float* noise  = (const float*)d_in[11];
    float* out = (float*)d_out;

    const int total = BB * CC;                 // 65536 threads
    const int threads = 128;
    const int blocks = total / threads;        // 512 CTAs -> 4/SM, one wave on 128 SMs
    accum_rnn_kernel<<<blocks, threads>>>(
        logits, iscale, nstd, ipw, ipb, W, cw, evw, evb, cbias, cmat, noise, out);
}